// round 15
// baseline (speedup 1.0000x reference)
#include <cuda_runtime.h>
#include <math.h>
#include <stdint.h>

#define BATCH 32
#define SEQ   2048
#define HID   512

typedef unsigned long long ull;

// Scratch (static device globals: allocation-free)
__device__ float g_xproj[SEQ * BATCH * HID];   // [s][b][h] layout
__device__ float g_hfin[BATCH * HID];          // final hidden state

// ---------------------------------------------------------------------------
// packed f32x2 helpers (FFMA2 only reachable via PTX)
// ---------------------------------------------------------------------------
__device__ __forceinline__ void ffma2(ull& acc, ull a, ull b) {
    asm("fma.rn.f32x2 %0, %1, %2, %0;" : "+l"(acc) : "l"(a), "l"(b));
}
__device__ __forceinline__ ull dup2(float v) {
    ull r; asm("mov.b64 %0, {%1, %1};" : "=l"(r) : "f"(v)); return r;
}
__device__ __forceinline__ float2 unpk(ull v) {
    float2 r; asm("mov.b64 {%0, %1}, %2;" : "=f"(r.x), "=f"(r.y) : "l"(v)); return r;
}
// fast tanh: 1 - 2/(e^{2x}+1); saturates to +-1, no NaN path.
__device__ __forceinline__ float ftanh(float x) {
    float e = __expf(x + x);
    return 1.f - __fdividef(2.f, e + 1.f);
}

// ---------------------------------------------------------------------------
// Kernel 1: xproj = x @ W_xh^T + (b_xh + b_hh + b_h), written as [s][b][h]
// (unchanged: 128x128 tile, FFMA2, reg double-buffer)
// ---------------------------------------------------------------------------
__global__ __launch_bounds__(256, 2) void xproj_gemm(
    const float* __restrict__ X,
    const float* __restrict__ Wxh,
    const float* __restrict__ bxh,
    const float* __restrict__ bhh,
    const float* __restrict__ bh)
{
    __shared__ float As[8][128];
    __shared__ float Bs[8][128];
    const int K = HID;
    const int n0 = blockIdx.x * 128;
    const int m0 = blockIdx.y * 128;
    const int tid = threadIdx.x;

    const int lr = tid >> 1;
    const int lc = (tid & 1) << 2;
    const int ca = (tid & 15) << 2;
    const int ra = (tid >> 4) << 2;

    ull acc[8][4];
#pragma unroll
    for (int i = 0; i < 8; i++)
#pragma unroll
        for (int j = 0; j < 4; j++) acc[i][j] = 0ull;

    const float* Aptr = X   + (size_t)(m0 + lr) * K + lc;
    const float* Bptr = Wxh + (size_t)(n0 + lr) * K + lc;

    float4 a4 = *(const float4*)(Aptr);
    float4 b4 = *(const float4*)(Bptr);

    for (int k0 = 0; k0 < K; k0 += 8) {
        As[lc + 0][lr] = a4.x; As[lc + 1][lr] = a4.y;
        As[lc + 2][lr] = a4.z; As[lc + 3][lr] = a4.w;
        Bs[lc + 0][lr] = b4.x; Bs[lc + 1][lr] = b4.y;
        Bs[lc + 2][lr] = b4.z; Bs[lc + 3][lr] = b4.w;
        __syncthreads();
        if (k0 + 8 < K) {
            a4 = *(const float4*)(Aptr + k0 + 8);
            b4 = *(const float4*)(Bptr + k0 + 8);
        }
#pragma unroll
        for (int k = 0; k < 8; k++) {
            float am[8];
            *(float4*)&am[0] = *(const float4*)&As[k][ra];
            *(float4*)&am[4] = *(const float4*)&As[k][ra + 64];
            ulonglong2 b01 = *(const ulonglong2*)&Bs[k][ca];
            ulonglong2 b23 = *(const ulonglong2*)&Bs[k][ca + 64];
#pragma unroll
            for (int i = 0; i < 8; i++) {
                ull ad = dup2(am[i]);
                ffma2(acc[i][0], ad, b01.x);
                ffma2(acc[i][1], ad, b01.y);
                ffma2(acc[i][2], ad, b23.x);
                ffma2(acc[i][3], ad, b23.y);
            }
        }
        __syncthreads();
    }

    float biasv[8];
#pragma unroll
    for (int j = 0; j < 8; j++) {
        int n = n0 + ((j < 4) ? (ca + j) : (64 + ca + j - 4));
        biasv[j] = bxh[n] + bhh[n] + bh[n];
    }

#pragma unroll
    for (int i = 0; i < 8; i++) {
        int m = m0 + ((i < 4) ? (ra + i) : (64 + ra + i - 4));
        int b = m >> 11;
        int s = m & (SEQ - 1);
        float* outr = &g_xproj[((size_t)s * BATCH + b) * HID + n0];
        float2 p0 = unpk(acc[i][0]);
        float2 p1 = unpk(acc[i][1]);
        float2 p2 = unpk(acc[i][2]);
        float2 p3 = unpk(acc[i][3]);
        float4 v0, v1;
        v0.x = p0.x + biasv[0]; v0.y = p0.y + biasv[1];
        v0.z = p1.x + biasv[2]; v0.w = p1.y + biasv[3];
        v1.x = p2.x + biasv[4]; v1.y = p2.y + biasv[5];
        v1.z = p3.x + biasv[6]; v1.w = p3.y + biasv[7];
        *(float4*)&outr[ca]      = v0;
        *(float4*)&outr[64 + ca] = v1;
    }
}

// ---------------------------------------------------------------------------
// Kernel 2: persistent recurrent scan — PULL model.
// 16 clusters x 8 CTAs; cluster = 2 batches, CTA rank = 64 hidden rows.
// RF weights, fold+butterfly reduce, quarter-split consumption (unchanged).
// Producers write ONLY locally: rep lanes STS into hs[nxt][rank], bar.sync,
// tid0 release-stores a monotonic flag (cluster scope; cumulativity over the
// bar covers all warps' STS). Consumers: puller warp p (p<8, p!=rank) polls
// peer p's flag via remote ld.acquire, pulls the 512B slice with 64 raw
// ld.shared::cluster.b64 (no engine, no tx), STS locally, and arrives on the
// LOCAL quarter-(p>>1) mbarrier (count 2, auto-reset; own quarter count 1).
// ---------------------------------------------------------------------------
__global__ __launch_bounds__(512, 1) __cluster_dims__(8, 1, 1)
void scan_kernel(const float* __restrict__ Whh)
{
    __shared__ __align__(16) float hs[2][8][2][64];  // [buf][rank][batch][row] 8KB
    __shared__ __align__(8) ull fullmb[2][4];        // [buf][quarter]
    __shared__ __align__(8) uint32_t stepflag;       // monotonic step counter

    const int tid = threadIdx.x;
    const int w = tid >> 5, l = tid & 31;

    unsigned rank;
    asm("mov.u32 %0, %%cluster_ctarank;" : "=r"(rank));
    const int b0 = (int)(blockIdx.x >> 3) * 2;
    const int i0 = (int)rank * 64;
    const int myq = (int)(rank >> 1);               // my quarter

    // Weights: rows i0+w*4+r, k = c*128 + l*4 + {0..3}, as f32x2 pairs.
    ull wp[4][4][2];
#pragma unroll
    for (int r = 0; r < 4; r++)
#pragma unroll
        for (int c = 0; c < 4; c++) {
            ulonglong2 u = *(const ulonglong2*)
                (&Whh[(size_t)(i0 + w * 4 + r) * HID + c * 128 + l * 4]);
            wp[r][c][0] = u.x; wp[r][c][1] = u.y;
        }

    uint32_t hbase  = (uint32_t)__cvta_generic_to_shared(&hs[0][0][0][0]);
    uint32_t mbbase = (uint32_t)__cvta_generic_to_shared(&fullmb[0][0]);
    uint32_t fbase  = (uint32_t)__cvta_generic_to_shared(&stepflag);

    // my flag in cluster address space (for the release store)
    uint32_t flagw;
    asm("mapa.shared::cluster.u32 %0, %1, %2;" : "=r"(flagw) : "r"(fbase), "r"(rank));

    // puller warp p (p<8, p!=rank): peer p's hs base + peer p's flag
    uint32_t psrc = 0, pflag = 0;
    const bool is_puller = (w < 8) && (w != (int)rank);
    if (w < 8) {
        asm("mapa.shared::cluster.u32 %0, %1, %2;" : "=r"(psrc)  : "r"(hbase), "r"(w));
        asm("mapa.shared::cluster.u32 %0, %1, %2;" : "=r"(pflag) : "r"(fbase), "r"(w));
        psrc += (uint32_t)(w * 512 + l * 16);   // slice [w], lane's 16B chunk
    }
    // local STS target for pulled data
    float* pdst = &hs[0][w & 7][0][0] + l * 4;

    // rep lanes (l%4==0) own (batch brep, row w*4+rrep) after the fold-reduce
    const int brep = (l >> 2) & 1;
    const int rrep = ((l >> 3) & 1) * 2 + ((l >> 4) & 1);
    const bool isrep = ((l & 3) == 0);
    // self-STS address for rep lane: hs[nxt][rank][brep][w*4+rrep]
    float* selfp = &hs[0][rank][brep][w * 4 + rrep];

    // Init: h(0)=0; quarter mbarriers count 2 (1 for own quarter); flag=0.
    for (int i = tid; i < 2 * HID; i += 512) ((float*)hs[0])[i] = 0.f;
    if (tid == 0) {
        stepflag = 0u;
#pragma unroll
        for (int bfi = 0; bfi < 2; bfi++)
#pragma unroll
            for (int q = 0; q < 4; q++) {
                uint32_t cnt = (q == myq) ? 1u : 2u;
                asm volatile("mbarrier.init.shared.b64 [%0], %1;"
                             :: "r"(mbbase + (uint32_t)(bfi * 32 + q * 8)), "r"(cnt) : "memory");
            }
    }
    __syncthreads();
    asm volatile("barrier.cluster.arrive.aligned;" ::: "memory");
    asm volatile("barrier.cluster.wait.aligned;" ::: "memory");

    int pb0 = 0, pb1 = 0;   // wait parity per buffer (quarters flip together)

    // xproj prefetch ring, 2 deep, on rep lanes
    const float* xpp = &g_xproj[(size_t)(b0 + brep) * HID + i0 + w * 4 + rrep];
    float xpA = 0.f, xpB = 0.f;
    if (isrep) {
        xpA = __ldcg(xpp);
        xpB = __ldcg(xpp + BATCH * HID);
        xpp += 2 * (size_t)BATCH * HID;
    }

    // per-lane base offset into hs slab: h[b][kchunk c] = hb[c*256 + b*64]
    const int lbase = (l >> 4) * 128 + (l & 15) * 4;

    for (int s = 0; s < SEQ; s++) {
        const int cur = s & 1, nxt = cur ^ 1;
        const uint32_t mbQ = mbbase + (uint32_t)(cur * 32);
        const uint32_t P = (uint32_t)((cur == 0) ? pb0 : pb1);

        // prefetch xp[s+2] BEFORE the waits (hides DRAM latency)
        float xpC = 0.f;
        if (isrep && s + 2 < SEQ) { xpC = __ldcg(xpp); xpp += (size_t)BATCH * HID; }

        const float* hb = &hs[cur][0][0][0] + lbase;
        ull acc[2][4];   // [batch][row]
#pragma unroll
        for (int b = 0; b < 2; b++)
#pragma unroll
            for (int r = 0; r < 4; r++) acc[b][r] = 0ull;

        // ---- quarter pipeline: wait q -> compute K chunk q ----
#pragma unroll
        for (int q = 0; q < 4; q++) {
            if (s > 0) {
                asm volatile(
                    "{\n\t.reg .pred p;\n\t"
                    "W%=:\n\t"
                    "mbarrier.try_wait.parity.acquire.cta.shared::cta.b64 p, [%0], %1, 0x989680;\n\t"
                    "@!p bra W%=;\n\t}"
                    :: "r"(mbQ + (uint32_t)(q * 8)), "r"(P) : "memory");
            }
#pragma unroll
            for (int b = 0; b < 2; b++) {
                ulonglong2 hc = *(const ulonglong2*)(hb + q * 256 + b * 64);
#pragma unroll
                for (int r = 0; r < 4; r++) {
                    ffma2(acc[b][r], wp[r][q][0], hc.x);
                    ffma2(acc[b][r], wp[r][q][1], hc.y);
                }
            }
        }
        if (s > 0) { if (cur == 0) pb0 ^= 1; else pb1 ^= 1; }

        float v[8];
#pragma unroll
        for (int b = 0; b < 2; b++)
#pragma unroll
            for (int r = 0; r < 4; r++) {
                float2 u = unpk(acc[b][r]);
                v[b * 4 + r] = u.x + u.y;
            }

        // fold-reduce: 8 values -> 1 per lane (9 shfls total)
        {
            const unsigned FM = 0xffffffffu;
            int hi2 = (l >> 2) & 1;
#pragma unroll
            for (int i = 0; i < 4; i++) {
                float send = hi2 ? v[i] : v[i + 4];
                float recv = __shfl_xor_sync(FM, send, 4);
                v[i] = (hi2 ? v[i + 4] : v[i]) + recv;
            }
            int hi3 = (l >> 3) & 1;
#pragma unroll
            for (int i = 0; i < 2; i++) {
                float send = hi3 ? v[i] : v[i + 2];
                float recv = __shfl_xor_sync(FM, send, 8);
                v[i] = (hi3 ? v[i + 2] : v[i]) + recv;
            }
            int hi4 = (l >> 4) & 1;
            {
                float send = hi4 ? v[0] : v[1];
                float recv = __shfl_xor_sync(FM, send, 16);
                v[0] = (hi4 ? v[1] : v[0]) + recv;
            }
            v[0] += __shfl_xor_sync(FM, v[0], 1);
            v[0] += __shfl_xor_sync(FM, v[0], 2);
        }
        // rep lanes finish output; STS directly into local hs[nxt][rank]
        if (isrep)
            selfp[nxt * 1024] = ftanh(v[0] + xpA);   // 1024 floats = buf stride
        __syncthreads();

        // publish: my slice for step s+1 is ready (bar covers all STS;
        // release is cumulative over what tid0 observed at the bar)
        if (tid == 0)
            asm volatile("st.release.cluster.shared::cluster.u32 [%0], %1;"
                         :: "r"(flagw), "r"((uint32_t)(s + 1)) : "memory");

        // pullers: fetch peer w's slice for step s+1 into local hs[nxt][w]
        if (is_puller) {
            const uint32_t tgt = (uint32_t)(s + 1);
            uint32_t f;
            do {
                asm volatile("ld.acquire.cluster.shared::cluster.u32 %0, [%1];"
                             : "=r"(f) : "r"(pflag) : "memory");
            } while (f < tgt);
            ull d0, d1;
            const uint32_t src = psrc + (uint32_t)(nxt * 4096);
            asm volatile("ld.shared::cluster.b64 %0, [%1];" : "=l"(d0) : "r"(src) : "memory");
            asm volatile("ld.shared::cluster.b64 %0, [%1];" : "=l"(d1) : "r"(src + 8) : "memory");
            float* dp = pdst + nxt * 1024;
            *(ull*)(dp)     = d0;
            *(ull*)(dp + 2) = d1;
            __syncwarp();
            if (l == 0)
                asm volatile("mbarrier.arrive.shared.b64 _, [%0];"
                             :: "r"(mbbase + (uint32_t)(nxt * 32 + (w >> 1) * 8)) : "memory");
        }
        xpA = xpB; xpB = xpC;
    }

    // final: h(SEQ) pulled into hs[0] during s=SEQ-1; wait buf0 quarters
    {
        const uint32_t P = (uint32_t)pb0;
#pragma unroll
        for (int q = 0; q < 4; q++) {
            asm volatile(
                "{\n\t.reg .pred p;\n\t"
                "W%=:\n\t"
                "mbarrier.try_wait.parity.acquire.cta.shared::cta.b64 p, [%0], %1, 0x989680;\n\t"
                "@!p bra W%=;\n\t}"
                :: "r"(mbbase + (uint32_t)(q * 8)), "r"(P) : "memory");
        }
    }
    for (int idx = tid; idx < 2 * HID; idx += 512) {
        int b = idx >> 9;
        int k = idx & 511;
        g_hfin[(b0 + b) * HID + k] = hs[0][k >> 6][b][k & 63];
    }
}

// ---------------------------------------------------------------------------
// Kernel 3: out = h_final @ W_fc^T + b_fc.
// ---------------------------------------------------------------------------
__global__ __launch_bounds__(256) void fc_kernel(
    const float* __restrict__ Wfc, const float* __restrict__ bfc,
    float* __restrict__ out)
{
    __shared__ float hsm[HID];
    const int b = blockIdx.x;
    const int o0 = blockIdx.y * 32;
    const int tid = threadIdx.x;
    for (int i = tid; i < HID; i += 256) hsm[i] = g_hfin[b * HID + i];
    __syncthreads();
    const int w = tid >> 5, l = tid & 31;
#pragma unroll
    for (int oi = 0; oi < 4; oi++) {
        int o = o0 + w * 4 + oi;
        const float* wr = Wfc + (size_t)o * HID;
        float sum = 0.f;
#pragma unroll
        for (int j2 = 0; j2 < HID / 32; j2++)
            sum = fmaf(hsm[j2 * 32 + l], wr[j2 * 32 + l], sum);
#pragma unroll
        for (int off = 16; off > 0; off >>= 1)
            sum += __shfl_down_sync(0xffffffffu, sum, off);
        if (l == 0) out[b * HID + o] = sum + bfc[o];
    }
}

// ---------------------------------------------------------------------------
extern "C" void kernel_launch(void* const* d_in, const int* in_sizes, int n_in,
                              void* d_out, int out_size)
{
    const float* x   = (const float*)d_in[0];
    const float* Wxh = (const float*)d_in[1];
    const float* bxh = (const float*)d_in[2];
    const float* Whh = (const float*)d_in[3];
    const float* bhh = (const float*)d_in[4];
    const float* bh  = (const float*)d_in[5];
    const float* Wfc = (const float*)d_in[6];
    const float* bfc = (const float*)d_in[7];
    float* out = (float*)d_out;

    xproj_gemm<<<dim3(HID / 128, (BATCH * SEQ) / 128), 256>>>(x, Wxh, bxh, bhh, bh);
    scan_kernel<<<128, 512>>>(Whh);
    fc_kernel<<<dim3(BATCH, 16), 256>>>(Wfc, bfc, out);
}

// round 16
// speedup vs baseline: 1.1866x; 1.1866x over previous
#include <cuda_runtime.h>
#include <math.h>
#include <stdint.h>

#define BATCH 32
#define SEQ   2048
#define HID   512

typedef unsigned long long ull;

// Scratch (static device globals: allocation-free)
__device__ float g_xproj[SEQ * BATCH * HID];   // [s][b][h] layout
__device__ float g_hfin[BATCH * HID];          // final hidden state

// ---------------------------------------------------------------------------
// packed f32x2 helpers (FFMA2 only reachable via PTX)
// ---------------------------------------------------------------------------
__device__ __forceinline__ void ffma2(ull& acc, ull a, ull b) {
    asm("fma.rn.f32x2 %0, %1, %2, %0;" : "+l"(acc) : "l"(a), "l"(b));
}
__device__ __forceinline__ ull dup2(float v) {
    ull r; asm("mov.b64 %0, {%1, %1};" : "=l"(r) : "f"(v)); return r;
}
__device__ __forceinline__ float2 unpk(ull v) {
    float2 r; asm("mov.b64 {%0, %1}, %2;" : "=f"(r.x), "=f"(r.y) : "l"(v)); return r;
}
// fast tanh: 1 - 2/(e^{2x}+1); saturates to +-1, no NaN path.
__device__ __forceinline__ float ftanh(float x) {
    float e = __expf(x + x);
    return 1.f - __fdividef(2.f, e + 1.f);
}

// ---------------------------------------------------------------------------
// Kernel 1: xproj = x @ W_xh^T + (b_xh + b_hh + b_h), written as [s][b][h]
// (unchanged: 128x128 tile, FFMA2, reg double-buffer)
// ---------------------------------------------------------------------------
__global__ __launch_bounds__(256, 2) void xproj_gemm(
    const float* __restrict__ X,
    const float* __restrict__ Wxh,
    const float* __restrict__ bxh,
    const float* __restrict__ bhh,
    const float* __restrict__ bh)
{
    __shared__ float As[8][128];
    __shared__ float Bs[8][128];
    const int K = HID;
    const int n0 = blockIdx.x * 128;
    const int m0 = blockIdx.y * 128;
    const int tid = threadIdx.x;

    const int lr = tid >> 1;
    const int lc = (tid & 1) << 2;
    const int ca = (tid & 15) << 2;
    const int ra = (tid >> 4) << 2;

    ull acc[8][4];
#pragma unroll
    for (int i = 0; i < 8; i++)
#pragma unroll
        for (int j = 0; j < 4; j++) acc[i][j] = 0ull;

    const float* Aptr = X   + (size_t)(m0 + lr) * K + lc;
    const float* Bptr = Wxh + (size_t)(n0 + lr) * K + lc;

    float4 a4 = *(const float4*)(Aptr);
    float4 b4 = *(const float4*)(Bptr);

    for (int k0 = 0; k0 < K; k0 += 8) {
        As[lc + 0][lr] = a4.x; As[lc + 1][lr] = a4.y;
        As[lc + 2][lr] = a4.z; As[lc + 3][lr] = a4.w;
        Bs[lc + 0][lr] = b4.x; Bs[lc + 1][lr] = b4.y;
        Bs[lc + 2][lr] = b4.z; Bs[lc + 3][lr] = b4.w;
        __syncthreads();
        if (k0 + 8 < K) {
            a4 = *(const float4*)(Aptr + k0 + 8);
            b4 = *(const float4*)(Bptr + k0 + 8);
        }
#pragma unroll
        for (int k = 0; k < 8; k++) {
            float am[8];
            *(float4*)&am[0] = *(const float4*)&As[k][ra];
            *(float4*)&am[4] = *(const float4*)&As[k][ra + 64];
            ulonglong2 b01 = *(const ulonglong2*)&Bs[k][ca];
            ulonglong2 b23 = *(const ulonglong2*)&Bs[k][ca + 64];
#pragma unroll
            for (int i = 0; i < 8; i++) {
                ull ad = dup2(am[i]);
                ffma2(acc[i][0], ad, b01.x);
                ffma2(acc[i][1], ad, b01.y);
                ffma2(acc[i][2], ad, b23.x);
                ffma2(acc[i][3], ad, b23.y);
            }
        }
        __syncthreads();
    }

    float biasv[8];
#pragma unroll
    for (int j = 0; j < 8; j++) {
        int n = n0 + ((j < 4) ? (ca + j) : (64 + ca + j - 4));
        biasv[j] = bxh[n] + bhh[n] + bh[n];
    }

#pragma unroll
    for (int i = 0; i < 8; i++) {
        int m = m0 + ((i < 4) ? (ra + i) : (64 + ra + i - 4));
        int b = m >> 11;
        int s = m & (SEQ - 1);
        float* outr = &g_xproj[((size_t)s * BATCH + b) * HID + n0];
        float2 p0 = unpk(acc[i][0]);
        float2 p1 = unpk(acc[i][1]);
        float2 p2 = unpk(acc[i][2]);
        float2 p3 = unpk(acc[i][3]);
        float4 v0, v1;
        v0.x = p0.x + biasv[0]; v0.y = p0.y + biasv[1];
        v0.z = p1.x + biasv[2]; v0.w = p1.y + biasv[3];
        v1.x = p2.x + biasv[4]; v1.y = p2.y + biasv[5];
        v1.z = p3.x + biasv[6]; v1.w = p3.y + biasv[7];
        *(float4*)&outr[ca]      = v0;
        *(float4*)&outr[64 + ca] = v1;
    }
}

// ---------------------------------------------------------------------------
// Kernel 2: persistent recurrent scan. 16 clusters x 8 CTAs; cluster = 2
// batches, CTA rank = 64 hidden rows. RF weights, fold+butterfly reduce,
// quarter-split consumption (as R14). Exchange: marshal to LOCAL staging
// (2 STS.128/warp), bar.sync (drains local STS only), then warp w (w<8)
// stores the WHOLE 512B slice to peer w as ONE 32-lane coalesced v4 remote
// store, and every lane does mbarrier.arrive.release.cluster on peer w's
// quarter-(rank>>1) barrier (count 64 = 2 producer warps x 32 lanes,
// auto-reset). Each lane's release orders its own 16B store. No bulk engine,
// no tx arming, no fences, no remote-store drain at the bar.
// ---------------------------------------------------------------------------
__global__ __launch_bounds__(512, 1) __cluster_dims__(8, 1, 1)
void scan_kernel(const float* __restrict__ Whh)
{
    __shared__ __align__(16) float hs[2][8][2][64];  // [buf][rank][batch][row] 8KB
    __shared__ __align__(16) float outs[2][2][64];   // [parity][batch][row] 1KB
    __shared__ __align__(8) ull fullmb[2][4];        // [buf][quarter], count=64

    const int tid = threadIdx.x;
    const int w = tid >> 5, l = tid & 31;

    unsigned rank;
    asm("mov.u32 %0, %%cluster_ctarank;" : "=r"(rank));
    const int b0 = (int)(blockIdx.x >> 3) * 2;
    const int i0 = (int)rank * 64;
    const int myq = (int)(rank >> 1);               // my quarter

    // Weights: rows i0+w*4+r, k = c*128 + l*4 + {0..3}, as f32x2 pairs.
    ull wp[4][4][2];
#pragma unroll
    for (int r = 0; r < 4; r++)
#pragma unroll
        for (int c = 0; c < 4; c++) {
            ulonglong2 u = *(const ulonglong2*)
                (&Whh[(size_t)(i0 + w * 4 + r) * HID + c * 128 + l * 4]);
            wp[r][c][0] = u.x; wp[r][c][1] = u.y;
        }

    uint32_t hbase  = (uint32_t)__cvta_generic_to_shared(&hs[0][0][0][0]);
    uint32_t mbbase = (uint32_t)__cvta_generic_to_shared(&fullmb[0][0]);
    // local mbarrier addrs: fullmb[buf][q] = mbbase + buf*32 + q*8

    // storing warp w (w<8, incl. self): peer w's hs slot for MY slice (lane
    // chunk l*16) + peer w's quarter-(myq) mbarrier.
    uint32_t rdst = 0, rmb = 0;
    if (w < 8) {
        uint32_t rb;
        asm("mapa.shared::cluster.u32 %0, %1, %2;" : "=r"(rb) : "r"(hbase), "r"(w));
        rdst = rb + (uint32_t)(rank * 512 + l * 16);
        uint32_t rm;
        asm("mapa.shared::cluster.u32 %0, %1, %2;" : "=r"(rm) : "r"(mbbase), "r"(w));
        rmb = rm + (uint32_t)(myq * 8);
    }

    // every lane owns (batch brep, row w*4+rrep) after the fold-reduce
    const int brep = (l >> 2) & 1;
    const int rrep = ((l >> 3) & 1) * 2 + ((l >> 4) & 1);

    // Init: h(0)=0 in buf0; mbarriers count=64, auto-reset each phase.
    for (int i = tid; i < 2 * HID; i += 512) ((float*)hs[0])[i] = 0.f;
    if (tid == 0) {
#pragma unroll
        for (int bfi = 0; bfi < 2; bfi++)
#pragma unroll
            for (int q = 0; q < 4; q++)
                asm volatile("mbarrier.init.shared.b64 [%0], %1;"
                             :: "r"(mbbase + (uint32_t)(bfi * 32 + q * 8)), "r"(64u) : "memory");
    }
    __syncthreads();
    asm volatile("barrier.cluster.arrive.aligned;" ::: "memory");
    asm volatile("barrier.cluster.wait.aligned;" ::: "memory");

    int pb0 = 0, pb1 = 0;   // wait parity per buffer (quarters flip together)

    // xproj prefetch ring, 2 deep, all lanes
    const float* xpp = &g_xproj[(size_t)(b0 + brep) * HID + i0 + w * 4 + rrep];
    float xpA = __ldcg(xpp);
    float xpB = __ldcg(xpp + BATCH * HID);
    xpp += 2 * (size_t)BATCH * HID;

    // per-lane base offset into hs slab: h[b][kchunk c] = hb[c*256 + b*64]
    const int lbase = (l >> 4) * 128 + (l & 15) * 4;

    for (int s = 0; s < SEQ; s++) {
        const int cur = s & 1, nxt = cur ^ 1;
        const uint32_t mbQ = mbbase + (uint32_t)(cur * 32);
        const uint32_t P = (uint32_t)((cur == 0) ? pb0 : pb1);

        // prefetch xp[s+2] BEFORE the waits (hides DRAM latency)
        float xpC = 0.f;
        if (s + 2 < SEQ) { xpC = __ldcg(xpp); xpp += (size_t)BATCH * HID; }

        const float* hb = &hs[cur][0][0][0] + lbase;
        ull acc[2][4];   // [batch][row]
#pragma unroll
        for (int b = 0; b < 2; b++)
#pragma unroll
            for (int r = 0; r < 4; r++) acc[b][r] = 0ull;

        // ---- quarter pipeline: wait q -> compute K chunk q ----
#pragma unroll
        for (int q = 0; q < 4; q++) {
            if (s > 0) {
                asm volatile(
                    "{\n\t.reg .pred p;\n\t"
                    "W%=:\n\t"
                    "mbarrier.try_wait.parity.acquire.cluster.shared::cta.b64 p, [%0], %1, 0x989680;\n\t"
                    "@!p bra W%=;\n\t}"
                    :: "r"(mbQ + (uint32_t)(q * 8)), "r"(P) : "memory");
            }
#pragma unroll
            for (int b = 0; b < 2; b++) {
                ulonglong2 hc = *(const ulonglong2*)(hb + q * 256 + b * 64);
#pragma unroll
                for (int r = 0; r < 4; r++) {
                    ffma2(acc[b][r], wp[r][q][0], hc.x);
                    ffma2(acc[b][r], wp[r][q][1], hc.y);
                }
            }
        }
        if (s > 0) { if (cur == 0) pb0 ^= 1; else pb1 ^= 1; }

        float v[8];
#pragma unroll
        for (int b = 0; b < 2; b++)
#pragma unroll
            for (int r = 0; r < 4; r++) {
                float2 u = unpk(acc[b][r]);
                v[b * 4 + r] = u.x + u.y;
            }

        // fold-reduce: 8 values -> 1 per lane (9 shfls); every lane ends with
        // the full sum for its (brep, rrep).
        {
            const unsigned FM = 0xffffffffu;
            int hi2 = (l >> 2) & 1;
#pragma unroll
            for (int i = 0; i < 4; i++) {
                float send = hi2 ? v[i] : v[i + 4];
                float recv = __shfl_xor_sync(FM, send, 4);
                v[i] = (hi2 ? v[i + 4] : v[i]) + recv;
            }
            int hi3 = (l >> 3) & 1;
#pragma unroll
            for (int i = 0; i < 2; i++) {
                float send = hi3 ? v[i] : v[i + 2];
                float recv = __shfl_xor_sync(FM, send, 8);
                v[i] = (hi3 ? v[i + 2] : v[i]) + recv;
            }
            int hi4 = (l >> 4) & 1;
            {
                float send = hi4 ? v[0] : v[1];
                float recv = __shfl_xor_sync(FM, send, 16);
                v[0] = (hi4 ? v[1] : v[0]) + recv;
            }
            v[0] += __shfl_xor_sync(FM, v[0], 1);
            v[0] += __shfl_xor_sync(FM, v[0], 2);
        }
        float ft = ftanh(v[0] + xpA);

        // marshal rows 0..3 of batch (l&1) into lanes 0/1; 2 STS.128/warp
        // into local parity staging. source lane for (B, r):
        // (B<<2) | ((r>>1)<<3) | ((r&1)<<4)
        {
            const unsigned FM = 0xffffffffu;
            int Bsel = (l & 1) << 2;
            float t0 = __shfl_sync(FM, ft, Bsel);
            float t1 = __shfl_sync(FM, ft, Bsel | 16);
            float t2 = __shfl_sync(FM, ft, Bsel | 8);
            float t3 = __shfl_sync(FM, ft, Bsel | 24);
            if (l < 2)
                *(float4*)&outs[cur][l][w * 4] = make_float4(t0, t1, t2, t3);
        }

        // bar drains only the 32 local STS above (cheap).
        asm volatile("bar.sync 0, 512;" ::: "memory");

        // warp w (w<8): ONE coalesced 32-lane v4 store = whole 512B slice to
        // peer w, then per-lane release-arrive (orders own 16B store).
        if (w < 8) {
            float4 vv = *(const float4*)
                ((const char*)&outs[0][0][0] + cur * 512 + l * 16);
            asm volatile("st.shared::cluster.v4.f32 [%0], {%1, %2, %3, %4};"
                         :: "r"(rdst + (uint32_t)(nxt * 4096)),
                            "f"(vv.x), "f"(vv.y), "f"(vv.z), "f"(vv.w) : "memory");
            asm volatile("mbarrier.arrive.release.cluster.shared::cluster.b64 _, [%0];"
                         :: "r"(rmb + (uint32_t)(nxt * 32)) : "memory");
        }
        xpA = xpB; xpB = xpC;
    }

    // final: h(SEQ) lands in hs[0] (SEQ even) under buf0 quarters 0-3
    {
        const uint32_t P = (uint32_t)pb0;
#pragma unroll
        for (int q = 0; q < 4; q++) {
            asm volatile(
                "{\n\t.reg .pred p;\n\t"
                "W%=:\n\t"
                "mbarrier.try_wait.parity.acquire.cluster.shared::cta.b64 p, [%0], %1, 0x989680;\n\t"
                "@!p bra W%=;\n\t}"
                :: "r"(mbbase + (uint32_t)(q * 8)), "r"(P) : "memory");
        }
    }
    for (int idx = tid; idx < 2 * HID; idx += 512) {
        int b = idx >> 9;
        int k = idx & 511;
        g_hfin[(b0 + b) * HID + k] = hs[0][k >> 6][b][k & 63];
    }
}

// ---------------------------------------------------------------------------
// Kernel 3: out = h_final @ W_fc^T + b_fc.
// ---------------------------------------------------------------------------
__global__ __launch_bounds__(256) void fc_kernel(
    const float* __restrict__ Wfc, const float* __restrict__ bfc,
    float* __restrict__ out)
{
    __shared__ float hsm[HID];
    const int b = blockIdx.x;
    const int o0 = blockIdx.y * 32;
    const int tid = threadIdx.x;
    for (int i = tid; i < HID; i += 256) hsm[i] = g_hfin[b * HID + i];
    __syncthreads();
    const int w = tid >> 5, l = tid & 31;
#pragma unroll
    for (int oi = 0; oi < 4; oi++) {
        int o = o0 + w * 4 + oi;
        const float* wr = Wfc + (size_t)o * HID;
        float sum = 0.f;
#pragma unroll
        for (int j2 = 0; j2 < HID / 32; j2++)
            sum = fmaf(hsm[j2 * 32 + l], wr[j2 * 32 + l], sum);
#pragma unroll
        for (int off = 16; off > 0; off >>= 1)
            sum += __shfl_down_sync(0xffffffffu, sum, off);
        if (l == 0) out[b * HID + o] = sum + bfc[o];
    }
}

// ---------------------------------------------------------------------------
extern "C" void kernel_launch(void* const* d_in, const int* in_sizes, int n_in,
                              void* d_out, int out_size)
{
    const float* x   = (const float*)d_in[0];
    const float* Wxh = (const float*)d_in[1];
    const float* bxh = (const float*)d_in[2];
    const float* Whh = (const float*)d_in[3];
    const float* bhh = (const float*)d_in[4];
    const float* bh  = (const float*)d_in[5];
    const float* Wfc = (const float*)d_in[6];
    const float* bfc = (const float*)d_in[7];
    float* out = (float*)d_out;

    xproj_gemm<<<dim3(HID / 128, (BATCH * SEQ) / 128), 256>>>(x, Wxh, bxh, bhh, bh);
    scan_kernel<<<128, 512>>>(Whh);
    fc_kernel<<<dim3(BATCH, 16), 256>>>(Wfc, bfc, out);
}

// round 17
// speedup vs baseline: 1.4248x; 1.2007x over previous
#include <cuda_runtime.h>
#include <math.h>
#include <stdint.h>

#define BATCH 32
#define SEQ   2048
#define HID   512

typedef unsigned long long ull;

// Scratch (static device globals: allocation-free)
__device__ float g_xproj[SEQ * BATCH * HID];   // [s][b][h] layout
__device__ float g_hfin[BATCH * HID];          // final hidden state

// ---------------------------------------------------------------------------
// packed f32x2 helpers (FFMA2 only reachable via PTX)
// ---------------------------------------------------------------------------
__device__ __forceinline__ void ffma2(ull& acc, ull a, ull b) {
    asm("fma.rn.f32x2 %0, %1, %2, %0;" : "+l"(acc) : "l"(a), "l"(b));
}
__device__ __forceinline__ ull dup2(float v) {
    ull r; asm("mov.b64 %0, {%1, %1};" : "=l"(r) : "f"(v)); return r;
}
__device__ __forceinline__ float2 unpk(ull v) {
    float2 r; asm("mov.b64 {%0, %1}, %2;" : "=f"(r.x), "=f"(r.y) : "l"(v)); return r;
}
// fast tanh: 1 - 2/(e^{2x}+1); saturates to +-1, no NaN path.
__device__ __forceinline__ float ftanh(float x) {
    float e = __expf(x + x);
    return 1.f - __fdividef(2.f, e + 1.f);
}

// ---------------------------------------------------------------------------
// Kernel 1: xproj = x @ W_xh^T + (b_xh + b_hh + b_h), written as [s][b][h]
// This round: 2-stage smem double-buffer -> ONE __syncthreads per k-step.
// ---------------------------------------------------------------------------
__global__ __launch_bounds__(256, 2) void xproj_gemm(
    const float* __restrict__ X,
    const float* __restrict__ Wxh,
    const float* __restrict__ bxh,
    const float* __restrict__ bhh,
    const float* __restrict__ bh)
{
    __shared__ float As[2][8][128];
    __shared__ float Bs[2][8][128];
    const int K = HID;
    const int n0 = blockIdx.x * 128;
    const int m0 = blockIdx.y * 128;
    const int tid = threadIdx.x;

    const int lr = tid >> 1;
    const int lc = (tid & 1) << 2;
    const int ca = (tid & 15) << 2;
    const int ra = (tid >> 4) << 2;

    ull acc[8][4];
#pragma unroll
    for (int i = 0; i < 8; i++)
#pragma unroll
        for (int j = 0; j < 4; j++) acc[i][j] = 0ull;

    const float* Aptr = X   + (size_t)(m0 + lr) * K + lc;
    const float* Bptr = Wxh + (size_t)(n0 + lr) * K + lc;

    float4 a4 = *(const float4*)(Aptr);
    float4 b4 = *(const float4*)(Bptr);
    As[0][lc + 0][lr] = a4.x; As[0][lc + 1][lr] = a4.y;
    As[0][lc + 2][lr] = a4.z; As[0][lc + 3][lr] = a4.w;
    Bs[0][lc + 0][lr] = b4.x; Bs[0][lc + 1][lr] = b4.y;
    Bs[0][lc + 2][lr] = b4.z; Bs[0][lc + 3][lr] = b4.w;
    __syncthreads();

    int st = 0;
    for (int k0 = 0; k0 < K; k0 += 8) {
        if (k0 + 8 < K) {                       // prefetch next stage (regs)
            a4 = *(const float4*)(Aptr + k0 + 8);
            b4 = *(const float4*)(Bptr + k0 + 8);
        }
#pragma unroll
        for (int k = 0; k < 8; k++) {
            float am[8];
            *(float4*)&am[0] = *(const float4*)&As[st][k][ra];
            *(float4*)&am[4] = *(const float4*)&As[st][k][ra + 64];
            ulonglong2 b01 = *(const ulonglong2*)&Bs[st][k][ca];
            ulonglong2 b23 = *(const ulonglong2*)&Bs[st][k][ca + 64];
#pragma unroll
            for (int i = 0; i < 8; i++) {
                ull ad = dup2(am[i]);
                ffma2(acc[i][0], ad, b01.x);
                ffma2(acc[i][1], ad, b01.y);
                ffma2(acc[i][2], ad, b23.x);
                ffma2(acc[i][3], ad, b23.y);
            }
        }
        if (k0 + 8 < K) {
            int nst = st ^ 1;                   // write other buffer: no WAR
            As[nst][lc + 0][lr] = a4.x; As[nst][lc + 1][lr] = a4.y;
            As[nst][lc + 2][lr] = a4.z; As[nst][lc + 3][lr] = a4.w;
            Bs[nst][lc + 0][lr] = b4.x; Bs[nst][lc + 1][lr] = b4.y;
            Bs[nst][lc + 2][lr] = b4.z; Bs[nst][lc + 3][lr] = b4.w;
            __syncthreads();
            st = nst;
        }
    }

    float biasv[8];
#pragma unroll
    for (int j = 0; j < 8; j++) {
        int n = n0 + ((j < 4) ? (ca + j) : (64 + ca + j - 4));
        biasv[j] = bxh[n] + bhh[n] + bh[n];
    }

#pragma unroll
    for (int i = 0; i < 8; i++) {
        int m = m0 + ((i < 4) ? (ra + i) : (64 + ra + i - 4));
        int b = m >> 11;
        int s = m & (SEQ - 1);
        float* outr = &g_xproj[((size_t)s * BATCH + b) * HID + n0];
        float2 p0 = unpk(acc[i][0]);
        float2 p1 = unpk(acc[i][1]);
        float2 p2 = unpk(acc[i][2]);
        float2 p3 = unpk(acc[i][3]);
        float4 v0, v1;
        v0.x = p0.x + biasv[0]; v0.y = p0.y + biasv[1];
        v0.z = p1.x + biasv[2]; v0.w = p1.y + biasv[3];
        v1.x = p2.x + biasv[4]; v1.y = p2.y + biasv[5];
        v1.z = p3.x + biasv[6]; v1.w = p3.y + biasv[7];
        *(float4*)&outr[ca]      = v0;
        *(float4*)&outr[64 + ca] = v1;
    }
}

// ---------------------------------------------------------------------------
// Kernel 2: persistent recurrent scan. 16 clusters x 8 CTAs; cluster = 2
// batches, CTA rank = 64 hidden rows. RF weights (packed per relative-rank
// offset j so indexing stays static), fold+butterfly reduce. EIGHTH-split
// delivery: per-rank mbarriers (8/buffer, expect 512B each; own rank is
// self-STS, no barrier). Consumer processes chunks in order: self, rank+1,
// ..., rank+7. Producer tid0 issues its 7 bulk copies SERIALIZED in order
// peer = rank-1, rank-2, ... : producer r's copy to consumer p then sits at
// engine position (r-1-p) mod 8 == consumer p's pipeline slot for rank r,
// so every consumer's k-th needed slice arrives ~k*delta (skew-matched).
// ---------------------------------------------------------------------------
__global__ __launch_bounds__(512, 1) __cluster_dims__(8, 1, 1)
void scan_kernel(const float* __restrict__ Whh)
{
    __shared__ __align__(16) float hs[2][8][2][64];  // [buf][rank][batch][row] 8KB
    __shared__ __align__(8) ull fullmb[2][8];        // [buf][producer rank]
    __shared__ uint2 ctab[7];                        // (rdst, rmb) per issue slot

    const int tid = threadIdx.x;
    const int w = tid >> 5, l = tid & 31;

    unsigned rank;
    asm("mov.u32 %0, %%cluster_ctarank;" : "=r"(rank));
    const int b0 = (int)(blockIdx.x >> 3) * 2;
    const int i0 = (int)rank * 64;

    // Weights packed by relative chunk j: rank r=(rank+j)&7, row i0+w*4+r_,
    // k = r*64 + l*2 + {0,1} as one f32x2.
    ull wp2[4][8];
#pragma unroll
    for (int j = 0; j < 8; j++) {
        int r = ((int)rank + j) & 7;
#pragma unroll
        for (int r_ = 0; r_ < 4; r_++)
            wp2[r_][j] = *(const ull*)
                &Whh[(size_t)(i0 + w * 4 + r_) * HID + r * 64 + l * 2];
    }

    uint32_t hbase  = (uint32_t)__cvta_generic_to_shared(&hs[0][0][0][0]);
    uint32_t mbbase = (uint32_t)__cvta_generic_to_shared(&fullmb[0][0]);
    // fullmb[buf][r] = mbbase + buf*64 + r*8

    // issue table: slot t -> peer (rank-1-t)&7; dst = peer's slot for MY slice
    if (tid < 7) {
        int p = ((int)rank - 1 - tid) & 7;
        uint32_t rb, rm;
        asm("mapa.shared::cluster.u32 %0, %1, %2;" : "=r"(rb) : "r"(hbase), "r"(p));
        asm("mapa.shared::cluster.u32 %0, %1, %2;" : "=r"(rm) : "r"(mbbase), "r"(p));
        ctab[tid] = make_uint2(rb + (uint32_t)(rank * 512),
                               rm + (uint32_t)(rank * 8));
    }

    // every lane owns (batch brep, row w*4+rrep) after the fold-reduce
    const int brep = (l >> 2) & 1;
    const int rrep = ((l >> 3) & 1) * 2 + ((l >> 4) & 1);
    const bool isrep = ((l & 3) == 0);
    float* selfp = &hs[0][rank][brep][w * 4 + rrep];

    // Init: h(0)=0; mbarriers count=1; pre-arm buf1 (targets of s=0 copies).
    for (int i = tid; i < 2 * HID; i += 512) ((float*)hs[0])[i] = 0.f;
    if (tid == 0) {
#pragma unroll
        for (int bfi = 0; bfi < 2; bfi++)
#pragma unroll
            for (int r = 0; r < 8; r++)
                asm volatile("mbarrier.init.shared.b64 [%0], %1;"
                             :: "r"(mbbase + (uint32_t)(bfi * 64 + r * 8)), "r"(1u) : "memory");
#pragma unroll
        for (int r = 0; r < 8; r++)
            if (r != (int)rank)
                asm volatile("mbarrier.arrive.expect_tx.shared::cta.b64 _, [%0], %1;"
                             :: "r"(mbbase + (uint32_t)(64 + r * 8)), "r"(512u) : "memory");
    }
    __syncthreads();
    asm volatile("barrier.cluster.arrive.aligned;" ::: "memory");
    asm volatile("barrier.cluster.wait.aligned;" ::: "memory");

    int pb0 = 0, pb1 = 0;   // wait parity per buffer

    // xproj prefetch ring, 2 deep, on rep lanes
    const float* xpp = &g_xproj[(size_t)(b0 + brep) * HID + i0 + w * 4 + rrep];
    float xpA = 0.f, xpB = 0.f;
    if (isrep) {
        xpA = __ldcg(xpp);
        xpB = __ldcg(xpp + BATCH * HID);
        xpp += 2 * (size_t)BATCH * HID;
    }

    for (int s = 0; s < SEQ; s++) {
        const int cur = s & 1, nxt = cur ^ 1;
        const uint32_t mbB = mbbase + (uint32_t)(cur * 64);
        const uint32_t P = (uint32_t)((cur == 0) ? pb0 : pb1);

        // prefetch xp[s+2] BEFORE the waits (hides DRAM latency)
        float xpC = 0.f;
        if (isrep && s + 2 < SEQ) { xpC = __ldcg(xpp); xpp += (size_t)BATCH * HID; }

        const float* hcur = &hs[cur][0][0][0];
        ull acc[2][4];   // [batch][row]
#pragma unroll
        for (int b = 0; b < 2; b++)
#pragma unroll
            for (int r_ = 0; r_ < 4; r_++) acc[b][r_] = 0ull;

        // ---- chunk pipeline: j=0 self (no wait), then rank+1..rank+7 ----
#pragma unroll
        for (int j = 0; j < 8; j++) {
            int r = ((int)rank + j) & 7;
            if (j > 0) {
                const uint32_t mb = mbB + (uint32_t)(r * 8);
                if (s > 0) {
                    asm volatile(
                        "{\n\t.reg .pred p;\n\t"
                        "W%=:\n\t"
                        "mbarrier.try_wait.parity.acquire.cta.shared::cta.b64 p, [%0], %1, 0x989680;\n\t"
                        "@!p bra W%=;\n\t}"
                        :: "r"(mb), "r"(P) : "memory");
                }
                if (tid == 0)
                    asm volatile("mbarrier.arrive.expect_tx.shared::cta.b64 _, [%0], %1;"
                                 :: "r"(mb), "r"(512u) : "memory");
            }
            ull h0 = *(const ull*)(hcur + r * 128 + l * 2);
            ull h1 = *(const ull*)(hcur + r * 128 + 64 + l * 2);
#pragma unroll
            for (int r_ = 0; r_ < 4; r_++) {
                ffma2(acc[0][r_], wp2[r_][j], h0);
                ffma2(acc[1][r_], wp2[r_][j], h1);
            }
        }
        if (s > 0) { if (cur == 0) pb0 ^= 1; else pb1 ^= 1; }

        float v[8];
#pragma unroll
        for (int b = 0; b < 2; b++)
#pragma unroll
            for (int r_ = 0; r_ < 4; r_++) {
                float2 u = unpk(acc[b][r_]);
                v[b * 4 + r_] = u.x + u.y;
            }

        // fold-reduce: 8 values -> 1 per lane (9 shfls total)
        {
            const unsigned FM = 0xffffffffu;
            int hi2 = (l >> 2) & 1;
#pragma unroll
            for (int i = 0; i < 4; i++) {
                float send = hi2 ? v[i] : v[i + 4];
                float recv = __shfl_xor_sync(FM, send, 4);
                v[i] = (hi2 ? v[i + 4] : v[i]) + recv;
            }
            int hi3 = (l >> 3) & 1;
#pragma unroll
            for (int i = 0; i < 2; i++) {
                float send = hi3 ? v[i] : v[i + 2];
                float recv = __shfl_xor_sync(FM, send, 8);
                v[i] = (hi3 ? v[i + 2] : v[i]) + recv;
            }
            int hi4 = (l >> 4) & 1;
            {
                float send = hi4 ? v[0] : v[1];
                float recv = __shfl_xor_sync(FM, send, 16);
                v[0] = (hi4 ? v[1] : v[0]) + recv;
            }
            v[0] += __shfl_xor_sync(FM, v[0], 1);
            v[0] += __shfl_xor_sync(FM, v[0], 2);
        }
        // rep lanes finish output; STS directly into local hs[nxt][rank]
        if (isrep)
            selfp[nxt * 1024] = ftanh(v[0] + xpA);   // 1024 floats = buf stride
        __syncthreads();

        // tid0 issues 7 bulk copies SERIALIZED in rotated order (skew-match)
        if (tid == 0) {
            asm volatile("fence.proxy.async.shared::cta;" ::: "memory");
            const uint32_t src = hbase + (uint32_t)(nxt * 4096 + rank * 512);
#pragma unroll
            for (int t = 0; t < 7; t++) {
                uint2 c = ctab[t];
                asm volatile(
                    "cp.async.bulk.shared::cluster.shared::cta.mbarrier::complete_tx::bytes"
                    " [%0], [%1], %2, [%3];"
                    :: "r"(c.x + (uint32_t)(nxt * 4096)),
                       "r"(src),
                       "r"(512u),
                       "r"(c.y + (uint32_t)(nxt * 64))
                    : "memory");
            }
        }
        xpA = xpB; xpB = xpC;
    }

    // final: h(SEQ) lands in hs[0] (SEQ even); wait buf0 barriers (skip self)
    {
        const uint32_t P = (uint32_t)pb0;
#pragma unroll
        for (int j = 1; j < 8; j++) {
            int r = ((int)rank + j) & 7;
            asm volatile(
                "{\n\t.reg .pred p;\n\t"
                "W%=:\n\t"
                "mbarrier.try_wait.parity.acquire.cta.shared::cta.b64 p, [%0], %1, 0x989680;\n\t"
                "@!p bra W%=;\n\t}"
                :: "r"(mbbase + (uint32_t)(r * 8)), "r"(P) : "memory");
        }
    }
    for (int idx = tid; idx < 2 * HID; idx += 512) {
        int b = idx >> 9;
        int k = idx & 511;
        g_hfin[(b0 + b) * HID + k] = hs[0][k >> 6][b][k & 63];
    }
}

// ---------------------------------------------------------------------------
// Kernel 3: out = h_final @ W_fc^T + b_fc.
// ---------------------------------------------------------------------------
__global__ __launch_bounds__(256) void fc_kernel(
    const float* __restrict__ Wfc, const float* __restrict__ bfc,
    float* __restrict__ out)
{
    __shared__ float hsm[HID];
    const int b = blockIdx.x;
    const int o0 = blockIdx.y * 32;
    const int tid = threadIdx.x;
    for (int i = tid; i < HID; i += 256) hsm[i] = g_hfin[b * HID + i];
    __syncthreads();
    const int w = tid >> 5, l = tid & 31;
#pragma unroll
    for (int oi = 0; oi < 4; oi++) {
        int o = o0 + w * 4 + oi;
        const float* wr = Wfc + (size_t)o * HID;
        float sum = 0.f;
#pragma unroll
        for (int j2 = 0; j2 < HID / 32; j2++)
            sum = fmaf(hsm[j2 * 32 + l], wr[j2 * 32 + l], sum);
#pragma unroll
        for (int off = 16; off > 0; off >>= 1)
            sum += __shfl_down_sync(0xffffffffu, sum, off);
        if (l == 0) out[b * HID + o] = sum + bfc[o];
    }
}

// ---------------------------------------------------------------------------
extern "C" void kernel_launch(void* const* d_in, const int* in_sizes, int n_in,
                              void* d_out, int out_size)
{
    const float* x   = (const float*)d_in[0];
    const float* Wxh = (const float*)d_in[1];
    const float* bxh = (const float*)d_in[2];
    const float* Whh = (const float*)d_in[3];
    const float* bhh = (const float*)d_in[4];
    const float* bh  = (const float*)d_in[5];
    const float* Wfc = (const float*)d_in[6];
    const float* bfc = (const float*)d_in[7];
    float* out = (float*)d_out;

    xproj_gemm<<<dim3(HID / 128, (BATCH * SEQ) / 128), 256>>>(x, Wxh, bxh, bhh, bh);
    scan_kernel<<<128, 512>>>(Whh);
    fc_kernel<<<dim3(BATCH, 16), 256>>>(Wfc, bfc, out);
}